// round 10
// baseline (speedup 1.0000x reference)
#include <cuda_runtime.h>
#include <cstdint>

#define EMB     128
#define NQ      32
#define TILE    128
#define WPAD    132        // (WPAD/4)%8==1 -> conflict-free LDS.128 column walk
#define W4      33
#define NBLK    148
#define THREADS 512
#define NW      16         // warps per block
#define TOPK    10
#define NEG_HUGE (-3.402823466e38f)

// persistent scratch (no cudaMalloc allowed)
__device__ float    g_cv[NBLK * NW * 4 * TOPK];
__device__ int      g_ci[NBLK * NW * 4 * TOPK];
__device__ unsigned g_ctr = 0;               // wraps to 0 each launch

#define FMA2(a, b, c) asm("fma.rn.f32x2 %0, %1, %2, %0;" : "+l"(a) : "l"(b), "l"(c))
#define PACK2(d, x, y) asm("mov.b64 %0, {%1, %2};" : "=l"(d) \
                           : "r"(__float_as_uint(x)), "r"(__float_as_uint(y)))
#define CP_ASYNC16(dst, src, sz) \
    asm volatile("cp.async.cg.shared.global [%0], [%1], 16, %2;\n" \
                 :: "r"(dst), "l"(src), "r"(sz))
#define CP_COMMIT()  asm volatile("cp.async.commit_group;\n" ::: "memory")
#define CP_WAIT1()   asm volatile("cp.async.wait_group 1;\n" ::: "memory")

#define LO_F(u) __uint_as_float((unsigned)((u) & 0xffffffffull))
#define HI_F(u) __uint_as_float((unsigned)((u) >> 32))

// warp-cooperative top-10 insert into this warp's private list
#define INSERT(sval, qq, roff) do {                                            \
    bool cnd = ((sval) > thr[(qq)]) && (gbase + (roff) + tx < n);              \
    unsigned m = __ballot_sync(0xffffffffu, cnd);                              \
    while (m) {                                                                \
        int src = __ffs(m) - 1; m &= m - 1;                                    \
        float v = __shfl_sync(0xffffffffu, (sval), src);                       \
        if (v > thr[(qq)]) {                                                   \
            int gi = gbase + (roff) + src;                                     \
            float* lv = &wv[(w * 4 + (qq)) * TOPK];                            \
            int*   li = &wi[(w * 4 + (qq)) * TOPK];                            \
            float mn = lv[0]; int ms = 0;                                      \
            _Pragma("unroll")                                                  \
            for (int j = 1; j < TOPK; j++) { float t = lv[j]; if (t < mn) { mn = t; ms = j; } } \
            lv[ms] = v; li[ms] = gi;                                           \
            float nt = lv[0];                                                  \
            _Pragma("unroll")                                                  \
            for (int j = 1; j < TOPK; j++) nt = fminf(nt, lv[j]);              \
            thr[(qq)] = nt;                                                    \
        }                                                                      \
    }                                                                          \
} while (0)

__global__ __launch_bounds__(THREADS, 1)
void retr_kernel(const float* __restrict__ queries,
                 const float* __restrict__ corpus,
                 float* __restrict__ out, int out_size, int n, int nTiles)
{
    extern __shared__ float smem[];
    float* buf = smem;                          // 2 * TILE * WPAD
    float* qsm = buf + 2 * TILE * WPAD;         // EMB * NQ, layout [k][q] (natural)
    float* wv  = qsm + EMB * NQ;                // NW*4 lists * TOPK
    int*   wi  = (int*)(wv + NW * 4 * TOPK);

    int tid = threadIdx.x;
    int tx  = tid & 31;
    int w   = tid >> 5;        // warp 0..15
    int rg  = w & 1;           // row group: rows [rg*64, rg*64+64)
    int qg  = w >> 1;          // query group: queries [4qg, 4qg+4)
    int rbase = rg * 64;

    // ---- inline query normalization into qsm[k*NQ + q] ----
    if (tid < NQ) {
        const float4* qv = (const float4*)(queries + tid * EMB);
        float ss = 0.f;
        #pragma unroll
        for (int i = 0; i < 32; i++) {
            float4 v = qv[i];
            ss += v.x * v.x + v.y * v.y + v.z * v.z + v.w * v.w;
        }
        float inv = 1.0f / fmaxf(sqrtf(ss), 1e-12f);
        #pragma unroll
        for (int i = 0; i < 32; i++) {
            float4 v = qv[i];
            qsm[(4 * i + 0) * NQ + tid] = v.x * inv;
            qsm[(4 * i + 1) * NQ + tid] = v.y * inv;
            qsm[(4 * i + 2) * NQ + tid] = v.z * inv;
            qsm[(4 * i + 3) * NQ + tid] = v.w * inv;
        }
    }
    if (tid < NW * 4) {
        #pragma unroll
        for (int s = 0; s < TOPK; s++) { wv[tid * TOPK + s] = NEG_HUGE; wi[tid * TOPK + s] = 0; }
    }
    float thr[4];
    #pragma unroll
    for (int j = 0; j < 4; j++) thr[j] = NEG_HUGE;
    __syncthreads();

    // ---- cp.async staging: TILE rows x 128 floats ----
    auto issue = [&](int tile, int bsel) {
        int gb = tile * TILE;
        float* db = buf + bsel * TILE * WPAD;
        #pragma unroll
        for (int i = 0; i < 8; i++) {
            int idx = tid + THREADS * i;           // 0..4095
            int row = idx >> 5, c4 = idx & 31;
            int g   = gb + row;
            unsigned dst = (unsigned)__cvta_generic_to_shared(db + row * WPAD + c4 * 4);
            const float* src = corpus + (size_t)g * EMB + c4 * 4;
            int sz = (g < n) ? 16 : 0;             // sz=0 -> 16B zero-fill
            CP_ASYNC16(dst, src, sz);
        }
    };

    int myFirst = blockIdx.x;
    if (myFirst < nTiles) issue(myFirst, 0);
    CP_COMMIT();

    int b = 0;
    for (int tile = myFirst; tile < nTiles; tile += gridDim.x, b ^= 1) {
        int next = tile + gridDim.x;
        if (next < nTiles) issue(next, b ^ 1);
        CP_COMMIT();
        CP_WAIT1();
        __syncthreads();

        int gbase = tile * TILE;
        const float4* sct4 = (const float4*)(buf + b * TILE * WPAD);

        // ---- GEMM: 4 queries x 2 rows per thread, packed f32x2 ----
        // acc[p] pair layout: lo = q(2p)*row, hi = q(2p+1)*row  -> NO:
        // acc[p][r]: p selects query-pair (q0q1 / q2q3), value pair = that
        // query pair against single row r (corpus duplicated).
        unsigned long long acc[2][2];   // [qpair][row]
        unsigned long long nacc = 0ull; // (sumsq r0, sumsq r1)
        acc[0][0] = acc[0][1] = acc[1][0] = acc[1][1] = 0ull;

        #pragma unroll 4
        for (int k4 = 0; k4 < 32; k4++) {
            float4 c0 = sct4[(rbase + tx)      * W4 + k4];  // row r0, k4*4..+3
            float4 c1 = sct4[(rbase + 32 + tx) * W4 + k4];  // row r1
            float f0[4] = {c0.x, c0.y, c0.z, c0.w};
            float f1[4] = {c1.x, c1.y, c1.z, c1.w};
            #pragma unroll
            for (int j = 0; j < 4; j++) {
                int k = k4 * 4 + j;
                // one broadcast LDS.128: 4 query values = 2 natural pairs
                const ulonglong2* qp = (const ulonglong2*)(qsm + k * NQ + qg * 4);
                ulonglong2 q2 = *qp;          // x=(q0,q1) y=(q2,q3)
                unsigned long long cd0, cd1, cp;
                PACK2(cd0, f0[j], f0[j]);
                PACK2(cd1, f1[j], f1[j]);
                PACK2(cp,  f0[j], f1[j]);
                FMA2(acc[0][0], q2.x, cd0);
                FMA2(acc[0][1], q2.x, cd1);
                FMA2(acc[1][0], q2.y, cd0);
                FMA2(acc[1][1], q2.y, cd1);
                FMA2(nacc, cp, cp);
            }
        }

        // ---- epilogue: corpus-norm scale + top-10 insert ----
        float iv0 = 1.0f / fmaxf(sqrtf(LO_F(nacc)), 1e-12f);   // row r0
        float iv1 = 1.0f / fmaxf(sqrtf(HI_F(nacc)), 1e-12f);   // row r1
        #pragma unroll
        for (int p = 0; p < 2; p++) {
            float s00 = LO_F(acc[p][0]) * iv0;   // q(2p),   r0
            float s10 = HI_F(acc[p][0]) * iv0;   // q(2p+1), r0
            float s01 = LO_F(acc[p][1]) * iv1;   // q(2p),   r1
            float s11 = HI_F(acc[p][1]) * iv1;   // q(2p+1), r1
            INSERT(s00, 2 * p + 0, rbase);
            INSERT(s10, 2 * p + 1, rbase);
            INSERT(s01, 2 * p + 0, rbase + 32);
            INSERT(s11, 2 * p + 1, rbase + 32);
        }
        __syncthreads();     // all warps done with buf[b] before re-staging
    }

    // ---- dump per-warp candidate lists ----
    __syncwarp();
    for (int e = tx; e < 4 * TOPK; e += 32) {
        g_cv[(blockIdx.x * NW + w) * 4 * TOPK + e] = wv[w * 4 * TOPK + e];
        g_ci[(blockIdx.x * NW + w) * 4 * TOPK + e] = wi[w * 4 * TOPK + e];
    }
    __threadfence();

    __shared__ unsigned s_last;
    if (tid == 0) {
        unsigned old = atomicInc(&g_ctr, NBLK - 1);
        s_last = (old == NBLK - 1) ? 1u : 0u;
    }
    __syncthreads();
    if (!s_last) return;
    __threadfence();

    // ---- final merge: 16 threads per query over 148 blocks x 2 lists ----
    int q = tid >> 4, part = tid & 15;
    int qgq = q >> 2, qq = q & 3;
    float lv[TOPK]; int li[TOPK];
    #pragma unroll
    for (int j = 0; j < TOPK; j++) { lv[j] = NEG_HUGE; li[j] = 0x7fffffff; }
    for (int blk = part; blk < NBLK; blk += 16) {
        #pragma unroll
        for (int rsel = 0; rsel < 2; rsel++) {
            int wl = qgq * 2 + rsel;
            int base = ((blk * NW + wl) * 4 + qq) * TOPK;
            #pragma unroll
            for (int s = 0; s < TOPK; s++) {
                float v = g_cv[base + s]; int gi = g_ci[base + s];
                float mn = lv[0]; int ms = 0;
                #pragma unroll
                for (int j = 1; j < TOPK; j++) if (lv[j] < mn) { mn = lv[j]; ms = j; }
                if (v > mn) { lv[ms] = v; li[ms] = gi; }
            }
        }
    }
    float* mv = buf;                          // tile buffers reusable now
    int*   mi = (int*)(buf + THREADS * TOPK);
    #pragma unroll
    for (int j = 0; j < TOPK; j++) { mv[tid * TOPK + j] = lv[j]; mi[tid * TOPK + j] = li[j]; }
    __syncthreads();

    if (part == 0) {
        float l3[TOPK]; int i3[TOPK];
        #pragma unroll
        for (int j = 0; j < TOPK; j++) { l3[j] = NEG_HUGE; i3[j] = 0x7fffffff; }
        for (int t = 0; t < 16 * TOPK; t++) {
            float v = mv[(q * 16) * TOPK + t]; int gi = mi[(q * 16) * TOPK + t];
            float mn = l3[0]; int ms = 0;
            #pragma unroll
            for (int j = 1; j < TOPK; j++) if (l3[j] < mn) { mn = l3[j]; ms = j; }
            if (v > mn) { l3[ms] = v; i3[ms] = gi; }
        }
        // sort desc, ties -> lower index (matches lax.top_k)
        for (int a = 0; a < TOPK; a++) {
            int best = a;
            for (int bb = a + 1; bb < TOPK; bb++)
                if (l3[bb] > l3[best] ||
                    (l3[bb] == l3[best] && i3[bb] < i3[best])) best = bb;
            float tv = l3[a]; l3[a] = l3[best]; l3[best] = tv;
            int   ti = i3[a]; i3[a] = i3[best]; i3[best] = ti;
        }
        if (out_size >= 2 * NQ * TOPK) {
            for (int j = 0; j < TOPK; j++) {
                out[q * TOPK + j] = l3[j];
                out[NQ * TOPK + q * TOPK + j] = (float)i3[j];
            }
        } else {
            for (int j = 0; j < TOPK; j++)
                if (q * TOPK + j < out_size) out[q * TOPK + j] = l3[j];
        }
    }
}

extern "C" void kernel_launch(void* const* d_in, const int* in_sizes, int n_in,
                              void* d_out, int out_size) {
    const float* queries = (const float*)d_in[0];
    const float* corpus  = (const float*)d_in[1];
    int n = in_sizes[1] / EMB;
    int nTiles = (n + TILE - 1) / TILE;

    size_t smemBytes = (size_t)(2 * TILE * WPAD + EMB * NQ) * sizeof(float)
                     + (size_t)(NW * 4 * TOPK) * (sizeof(float) + sizeof(int));
    cudaFuncSetAttribute(retr_kernel,
                         cudaFuncAttributeMaxDynamicSharedMemorySize, (int)smemBytes);

    retr_kernel<<<NBLK, THREADS, smemBytes>>>(queries, corpus, (float*)d_out,
                                              out_size, n, nTiles);
}

// round 11
// speedup vs baseline: 1.0020x; 1.0020x over previous
#include <cuda_runtime.h>
#include <cstdint>

#define EMB     128
#define NQ      32
#define TILE    128
#define WPAD    132        // (WPAD/4)%8==1 -> conflict-free LDS.128 column walk
#define W4      33
#define NBLK    148
#define THREADS 512
#define NW      16         // warps per block
#define TOPK    10
#define NEG_HUGE (-3.402823466e38f)

// persistent scratch (no cudaMalloc allowed)
__device__ float    g_cv[NBLK * NW * 4 * TOPK];
__device__ int      g_ci[NBLK * NW * 4 * TOPK];
__device__ unsigned g_ctr = 0;               // wraps to 0 each launch

#define FMA2(a, b, c) asm("fma.rn.f32x2 %0, %1, %2, %0;" : "+l"(a) : "l"(b), "l"(c))
#define PACK2(d, x, y) asm("mov.b64 %0, {%1, %2};" : "=l"(d) \
                           : "r"(__float_as_uint(x)), "r"(__float_as_uint(y)))
#define CP_ASYNC16(dst, src, sz) \
    asm volatile("cp.async.cg.shared.global [%0], [%1], 16, %2;\n" \
                 :: "r"(dst), "l"(src), "r"(sz))
#define CP_COMMIT()  asm volatile("cp.async.commit_group;\n" ::: "memory")
#define CP_WAIT1()   asm volatile("cp.async.wait_group 1;\n" ::: "memory")

#define LO_F(u) __uint_as_float((unsigned)((u) & 0xffffffffull))
#define HI_F(u) __uint_as_float((unsigned)((u) >> 32))

// warp-cooperative top-10 insert into this warp's private list
#define INSERT(sval, qq, roff) do {                                            \
    bool cnd = ((sval) > thr[(qq)]) && (gbase + (roff) + tx < n);              \
    unsigned m = __ballot_sync(0xffffffffu, cnd);                              \
    while (m) {                                                                \
        int src = __ffs(m) - 1; m &= m - 1;                                    \
        float v = __shfl_sync(0xffffffffu, (sval), src);                       \
        if (v > thr[(qq)]) {                                                   \
            int gi = gbase + (roff) + src;                                     \
            float* lv = &wv[(w * 4 + (qq)) * TOPK];                            \
            int*   li = &wi[(w * 4 + (qq)) * TOPK];                            \
            float mn = lv[0]; int ms = 0;                                      \
            _Pragma("unroll")                                                  \
            for (int j = 1; j < TOPK; j++) { float t = lv[j]; if (t < mn) { mn = t; ms = j; } } \
            lv[ms] = v; li[ms] = gi;                                           \
            float nt = lv[0];                                                  \
            _Pragma("unroll")                                                  \
            for (int j = 1; j < TOPK; j++) nt = fminf(nt, lv[j]);              \
            thr[(qq)] = nt;                                                    \
        }                                                                      \
    }                                                                          \
} while (0)

__global__ __launch_bounds__(THREADS, 1)
void retr_kernel(const float* __restrict__ queries,
                 const float* __restrict__ corpus,
                 float* __restrict__ out, int out_size, int n, int nTiles)
{
    extern __shared__ float smem[];
    float* buf = smem;                          // 2 * TILE * WPAD
    float* qsm = buf + 2 * TILE * WPAD;         // EMB * NQ, layout [k][q] (natural)
    float* wv  = qsm + EMB * NQ;                // NW*4 lists * TOPK
    int*   wi  = (int*)(wv + NW * 4 * TOPK);

    int tid = threadIdx.x;
    int tx  = tid & 31;
    int w   = tid >> 5;        // warp 0..15
    int rg  = w & 1;           // row group: rows [rg*64, rg*64+64)
    int qg  = w >> 1;          // query group: queries [4qg, 4qg+4)
    int rbase = rg * 64;

    // ---- inline query normalization into qsm[k*NQ + q] ----
    if (tid < NQ) {
        const float4* qv = (const float4*)(queries + tid * EMB);
        float ss = 0.f;
        #pragma unroll
        for (int i = 0; i < 32; i++) {
            float4 v = qv[i];
            ss += v.x * v.x + v.y * v.y + v.z * v.z + v.w * v.w;
        }
        float inv = 1.0f / fmaxf(sqrtf(ss), 1e-12f);
        #pragma unroll
        for (int i = 0; i < 32; i++) {
            float4 v = qv[i];
            qsm[(4 * i + 0) * NQ + tid] = v.x * inv;
            qsm[(4 * i + 1) * NQ + tid] = v.y * inv;
            qsm[(4 * i + 2) * NQ + tid] = v.z * inv;
            qsm[(4 * i + 3) * NQ + tid] = v.w * inv;
        }
    }
    if (tid < NW * 4) {
        #pragma unroll
        for (int s = 0; s < TOPK; s++) { wv[tid * TOPK + s] = NEG_HUGE; wi[tid * TOPK + s] = 0; }
    }
    float thr[4];
    #pragma unroll
    for (int j = 0; j < 4; j++) thr[j] = NEG_HUGE;
    __syncthreads();

    // ---- cp.async staging: TILE rows x 128 floats ----
    auto issue = [&](int tile, int bsel) {
        int gb = tile * TILE;
        float* db = buf + bsel * TILE * WPAD;
        #pragma unroll
        for (int i = 0; i < 8; i++) {
            int idx = tid + THREADS * i;           // 0..4095
            int row = idx >> 5, c4 = idx & 31;
            int g   = gb + row;
            unsigned dst = (unsigned)__cvta_generic_to_shared(db + row * WPAD + c4 * 4);
            const float* src = corpus + (size_t)g * EMB + c4 * 4;
            int sz = (g < n) ? 16 : 0;             // sz=0 -> 16B zero-fill
            CP_ASYNC16(dst, src, sz);
        }
    };

    int myFirst = blockIdx.x;
    if (myFirst < nTiles) issue(myFirst, 0);
    CP_COMMIT();

    int b = 0;
    for (int tile = myFirst; tile < nTiles; tile += gridDim.x, b ^= 1) {
        int next = tile + gridDim.x;
        if (next < nTiles) issue(next, b ^ 1);
        CP_COMMIT();
        CP_WAIT1();
        __syncthreads();

        int gbase = tile * TILE;
        const float4* sct4 = (const float4*)(buf + b * TILE * WPAD);

        // ---- GEMM: 4 queries x 2 rows per thread, packed f32x2 ----
        // acc[p] pair layout: lo = q(2p)*row, hi = q(2p+1)*row  -> NO:
        // acc[p][r]: p selects query-pair (q0q1 / q2q3), value pair = that
        // query pair against single row r (corpus duplicated).
        unsigned long long acc[2][2];   // [qpair][row]
        unsigned long long nacc = 0ull; // (sumsq r0, sumsq r1)
        acc[0][0] = acc[0][1] = acc[1][0] = acc[1][1] = 0ull;

        #pragma unroll 4
        for (int k4 = 0; k4 < 32; k4++) {
            float4 c0 = sct4[(rbase + tx)      * W4 + k4];  // row r0, k4*4..+3
            float4 c1 = sct4[(rbase + 32 + tx) * W4 + k4];  // row r1
            float f0[4] = {c0.x, c0.y, c0.z, c0.w};
            float f1[4] = {c1.x, c1.y, c1.z, c1.w};
            #pragma unroll
            for (int j = 0; j < 4; j++) {
                int k = k4 * 4 + j;
                // one broadcast LDS.128: 4 query values = 2 natural pairs
                const ulonglong2* qp = (const ulonglong2*)(qsm + k * NQ + qg * 4);
                ulonglong2 q2 = *qp;          // x=(q0,q1) y=(q2,q3)
                unsigned long long cd0, cd1, cp;
                PACK2(cd0, f0[j], f0[j]);
                PACK2(cd1, f1[j], f1[j]);
                PACK2(cp,  f0[j], f1[j]);
                FMA2(acc[0][0], q2.x, cd0);
                FMA2(acc[0][1], q2.x, cd1);
                FMA2(acc[1][0], q2.y, cd0);
                FMA2(acc[1][1], q2.y, cd1);
                FMA2(nacc, cp, cp);
            }
        }

        // ---- epilogue: corpus-norm scale + top-10 insert ----
        float iv0 = 1.0f / fmaxf(sqrtf(LO_F(nacc)), 1e-12f);   // row r0
        float iv1 = 1.0f / fmaxf(sqrtf(HI_F(nacc)), 1e-12f);   // row r1
        #pragma unroll
        for (int p = 0; p < 2; p++) {
            float s00 = LO_F(acc[p][0]) * iv0;   // q(2p),   r0
            float s10 = HI_F(acc[p][0]) * iv0;   // q(2p+1), r0
            float s01 = LO_F(acc[p][1]) * iv1;   // q(2p),   r1
            float s11 = HI_F(acc[p][1]) * iv1;   // q(2p+1), r1
            INSERT(s00, 2 * p + 0, rbase);
            INSERT(s10, 2 * p + 1, rbase);
            INSERT(s01, 2 * p + 0, rbase + 32);
            INSERT(s11, 2 * p + 1, rbase + 32);
        }
        __syncthreads();     // all warps done with buf[b] before re-staging
    }

    // ---- dump per-warp candidate lists ----
    __syncwarp();
    for (int e = tx; e < 4 * TOPK; e += 32) {
        g_cv[(blockIdx.x * NW + w) * 4 * TOPK + e] = wv[w * 4 * TOPK + e];
        g_ci[(blockIdx.x * NW + w) * 4 * TOPK + e] = wi[w * 4 * TOPK + e];
    }
    __threadfence();

    __shared__ unsigned s_last;
    if (tid == 0) {
        unsigned old = atomicInc(&g_ctr, NBLK - 1);
        s_last = (old == NBLK - 1) ? 1u : 0u;
    }
    __syncthreads();
    if (!s_last) return;
    __threadfence();

    // ---- final merge: 16 threads per query over 148 blocks x 2 lists ----
    int q = tid >> 4, part = tid & 15;
    int qgq = q >> 2, qq = q & 3;
    float lv[TOPK]; int li[TOPK];
    #pragma unroll
    for (int j = 0; j < TOPK; j++) { lv[j] = NEG_HUGE; li[j] = 0x7fffffff; }
    for (int blk = part; blk < NBLK; blk += 16) {
        #pragma unroll
        for (int rsel = 0; rsel < 2; rsel++) {
            int wl = qgq * 2 + rsel;
            int base = ((blk * NW + wl) * 4 + qq) * TOPK;
            #pragma unroll
            for (int s = 0; s < TOPK; s++) {
                float v = g_cv[base + s]; int gi = g_ci[base + s];
                float mn = lv[0]; int ms = 0;
                #pragma unroll
                for (int j = 1; j < TOPK; j++) if (lv[j] < mn) { mn = lv[j]; ms = j; }
                if (v > mn) { lv[ms] = v; li[ms] = gi; }
            }
        }
    }
    float* mv = buf;                          // tile buffers reusable now
    int*   mi = (int*)(buf + THREADS * TOPK);
    #pragma unroll
    for (int j = 0; j < TOPK; j++) { mv[tid * TOPK + j] = lv[j]; mi[tid * TOPK + j] = li[j]; }
    __syncthreads();

    if (part == 0) {
        float l3[TOPK]; int i3[TOPK];
        #pragma unroll
        for (int j = 0; j < TOPK; j++) { l3[j] = NEG_HUGE; i3[j] = 0x7fffffff; }
        for (int t = 0; t < 16 * TOPK; t++) {
            float v = mv[(q * 16) * TOPK + t]; int gi = mi[(q * 16) * TOPK + t];
            float mn = l3[0]; int ms = 0;
            #pragma unroll
            for (int j = 1; j < TOPK; j++) if (l3[j] < mn) { mn = l3[j]; ms = j; }
            if (v > mn) { l3[ms] = v; i3[ms] = gi; }
        }
        // sort desc, ties -> lower index (matches lax.top_k)
        for (int a = 0; a < TOPK; a++) {
            int best = a;
            for (int bb = a + 1; bb < TOPK; bb++)
                if (l3[bb] > l3[best] ||
                    (l3[bb] == l3[best] && i3[bb] < i3[best])) best = bb;
            float tv = l3[a]; l3[a] = l3[best]; l3[best] = tv;
            int   ti = i3[a]; i3[a] = i3[best]; i3[best] = ti;
        }
        if (out_size >= 2 * NQ * TOPK) {
            for (int j = 0; j < TOPK; j++) {
                out[q * TOPK + j] = l3[j];
                out[NQ * TOPK + q * TOPK + j] = (float)i3[j];
            }
        } else {
            for (int j = 0; j < TOPK; j++)
                if (q * TOPK + j < out_size) out[q * TOPK + j] = l3[j];
        }
    }
}

extern "C" void kernel_launch(void* const* d_in, const int* in_sizes, int n_in,
                              void* d_out, int out_size) {
    const float* queries = (const float*)d_in[0];
    const float* corpus  = (const float*)d_in[1];
    int n = in_sizes[1] / EMB;
    int nTiles = (n + TILE - 1) / TILE;

    size_t smemBytes = (size_t)(2 * TILE * WPAD + EMB * NQ) * sizeof(float)
                     + (size_t)(NW * 4 * TOPK) * (sizeof(float) + sizeof(int));
    cudaFuncSetAttribute(retr_kernel,
                         cudaFuncAttributeMaxDynamicSharedMemorySize, (int)smemBytes);

    retr_kernel<<<NBLK, THREADS, smemBytes>>>(queries, corpus, (float*)d_out,
                                              out_size, n, nTiles);
}

// round 12
// speedup vs baseline: 1.0058x; 1.0038x over previous
#include <cuda_runtime.h>
#include <cstdint>

#define EMB     128
#define NQ      32
#define TILE    128
#define WPAD    132        // (WPAD/4)%8==1 -> conflict-free LDS.128 column walk
#define W4      33
#define NBLK    148
#define THREADS 512
#define NW      16         // warps per block
#define TOPK    10
#define NEG_HUGE (-3.402823466e38f)

// persistent scratch (no cudaMalloc allowed)
__device__ float    g_cv[NBLK * NW * 4 * TOPK];
__device__ int      g_ci[NBLK * NW * 4 * TOPK];
__device__ unsigned g_ctr = 0;               // wraps to 0 each launch

#define FMA2(a, b, c) asm("fma.rn.f32x2 %0, %1, %2, %0;" : "+l"(a) : "l"(b), "l"(c))
#define PACK2(d, x, y) asm("mov.b64 %0, {%1, %2};" : "=l"(d) \
                           : "r"(__float_as_uint(x)), "r"(__float_as_uint(y)))
#define CP_ASYNC16(dst, src, sz) \
    asm volatile("cp.async.cg.shared.global [%0], [%1], 16, %2;\n" \
                 :: "r"(dst), "l"(src), "r"(sz))
#define CP_COMMIT()  asm volatile("cp.async.commit_group;\n" ::: "memory")
#define CP_WAIT1()   asm volatile("cp.async.wait_group 1;\n" ::: "memory")

#define LO_F(u) __uint_as_float((unsigned)((u) & 0xffffffffull))
#define HI_F(u) __uint_as_float((unsigned)((u) >> 32))

// warp-cooperative top-10 insert into this warp's private list
#define INSERT(sval, qq, roff) do {                                            \
    bool cnd = ((sval) > thr[(qq)]) && (gbase + (roff) + tx < n);              \
    unsigned m = __ballot_sync(0xffffffffu, cnd);                              \
    while (m) {                                                                \
        int src = __ffs(m) - 1; m &= m - 1;                                    \
        float v = __shfl_sync(0xffffffffu, (sval), src);                       \
        if (v > thr[(qq)]) {                                                   \
            int gi = gbase + (roff) + src;                                     \
            float* lv = &wv[(w * 4 + (qq)) * TOPK];                            \
            int*   li = &wi[(w * 4 + (qq)) * TOPK];                            \
            float mn = lv[0]; int ms = 0;                                      \
            _Pragma("unroll")                                                  \
            for (int j = 1; j < TOPK; j++) { float t = lv[j]; if (t < mn) { mn = t; ms = j; } } \
            lv[ms] = v; li[ms] = gi;                                           \
            float nt = lv[0];                                                  \
            _Pragma("unroll")                                                  \
            for (int j = 1; j < TOPK; j++) nt = fminf(nt, lv[j]);              \
            thr[(qq)] = nt;                                                    \
        }                                                                      \
    }                                                                          \
} while (0)

__global__ __launch_bounds__(THREADS, 1)
void retr_kernel(const float* __restrict__ queries,
                 const float* __restrict__ corpus,
                 float* __restrict__ out, int out_size, int n, int nTiles)
{
    extern __shared__ float smem[];
    float* buf = smem;                          // 2 * TILE * WPAD
    float* qsm = buf + 2 * TILE * WPAD;         // EMB * NQ, layout [k][q] (natural)
    float* wv  = qsm + EMB * NQ;                // NW*4 lists * TOPK
    int*   wi  = (int*)(wv + NW * 4 * TOPK);

    int tid = threadIdx.x;
    int tx  = tid & 31;
    int w   = tid >> 5;        // warp 0..15
    int rg  = w & 1;           // row group: rows [rg*64, rg*64+64)
    int qg  = w >> 1;          // query group: queries [4qg, 4qg+4)
    int rbase = rg * 64;

    // ---- inline query normalization into qsm[k*NQ + q] ----
    if (tid < NQ) {
        const float4* qv = (const float4*)(queries + tid * EMB);
        float ss = 0.f;
        #pragma unroll
        for (int i = 0; i < 32; i++) {
            float4 v = qv[i];
            ss += v.x * v.x + v.y * v.y + v.z * v.z + v.w * v.w;
        }
        float inv = 1.0f / fmaxf(sqrtf(ss), 1e-12f);
        #pragma unroll
        for (int i = 0; i < 32; i++) {
            float4 v = qv[i];
            qsm[(4 * i + 0) * NQ + tid] = v.x * inv;
            qsm[(4 * i + 1) * NQ + tid] = v.y * inv;
            qsm[(4 * i + 2) * NQ + tid] = v.z * inv;
            qsm[(4 * i + 3) * NQ + tid] = v.w * inv;
        }
    }
    if (tid < NW * 4) {
        #pragma unroll
        for (int s = 0; s < TOPK; s++) { wv[tid * TOPK + s] = NEG_HUGE; wi[tid * TOPK + s] = 0; }
    }
    float thr[4];
    #pragma unroll
    for (int j = 0; j < 4; j++) thr[j] = NEG_HUGE;
    __syncthreads();

    // ---- cp.async staging: TILE rows x 128 floats ----
    auto issue = [&](int tile, int bsel) {
        int gb = tile * TILE;
        float* db = buf + bsel * TILE * WPAD;
        #pragma unroll
        for (int i = 0; i < 8; i++) {
            int idx = tid + THREADS * i;           // 0..4095
            int row = idx >> 5, c4 = idx & 31;
            int g   = gb + row;
            unsigned dst = (unsigned)__cvta_generic_to_shared(db + row * WPAD + c4 * 4);
            const float* src = corpus + (size_t)g * EMB + c4 * 4;
            int sz = (g < n) ? 16 : 0;             // sz=0 -> 16B zero-fill
            CP_ASYNC16(dst, src, sz);
        }
    };

    int myFirst = blockIdx.x;
    if (myFirst < nTiles) issue(myFirst, 0);
    CP_COMMIT();

    int b = 0;
    for (int tile = myFirst; tile < nTiles; tile += gridDim.x, b ^= 1) {
        int next = tile + gridDim.x;
        if (next < nTiles) issue(next, b ^ 1);
        CP_COMMIT();
        CP_WAIT1();
        __syncthreads();

        int gbase = tile * TILE;
        const float4* sct4 = (const float4*)(buf + b * TILE * WPAD);

        // ---- GEMM: 4 queries x 2 rows per thread, packed f32x2 ----
        // acc[p] pair layout: lo = q(2p)*row, hi = q(2p+1)*row  -> NO:
        // acc[p][r]: p selects query-pair (q0q1 / q2q3), value pair = that
        // query pair against single row r (corpus duplicated).
        unsigned long long acc[2][2];   // [qpair][row]
        unsigned long long nacc = 0ull; // (sumsq r0, sumsq r1)
        acc[0][0] = acc[0][1] = acc[1][0] = acc[1][1] = 0ull;

        #pragma unroll 4
        for (int k4 = 0; k4 < 32; k4++) {
            float4 c0 = sct4[(rbase + tx)      * W4 + k4];  // row r0, k4*4..+3
            float4 c1 = sct4[(rbase + 32 + tx) * W4 + k4];  // row r1
            float f0[4] = {c0.x, c0.y, c0.z, c0.w};
            float f1[4] = {c1.x, c1.y, c1.z, c1.w};
            #pragma unroll
            for (int j = 0; j < 4; j++) {
                int k = k4 * 4 + j;
                // one broadcast LDS.128: 4 query values = 2 natural pairs
                const ulonglong2* qp = (const ulonglong2*)(qsm + k * NQ + qg * 4);
                ulonglong2 q2 = *qp;          // x=(q0,q1) y=(q2,q3)
                unsigned long long cd0, cd1, cp;
                PACK2(cd0, f0[j], f0[j]);
                PACK2(cd1, f1[j], f1[j]);
                PACK2(cp,  f0[j], f1[j]);
                FMA2(acc[0][0], q2.x, cd0);
                FMA2(acc[0][1], q2.x, cd1);
                FMA2(acc[1][0], q2.y, cd0);
                FMA2(acc[1][1], q2.y, cd1);
                FMA2(nacc, cp, cp);
            }
        }

        // ---- epilogue: corpus-norm scale + top-10 insert ----
        float iv0 = 1.0f / fmaxf(sqrtf(LO_F(nacc)), 1e-12f);   // row r0
        float iv1 = 1.0f / fmaxf(sqrtf(HI_F(nacc)), 1e-12f);   // row r1
        #pragma unroll
        for (int p = 0; p < 2; p++) {
            float s00 = LO_F(acc[p][0]) * iv0;   // q(2p),   r0
            float s10 = HI_F(acc[p][0]) * iv0;   // q(2p+1), r0
            float s01 = LO_F(acc[p][1]) * iv1;   // q(2p),   r1
            float s11 = HI_F(acc[p][1]) * iv1;   // q(2p+1), r1
            INSERT(s00, 2 * p + 0, rbase);
            INSERT(s10, 2 * p + 1, rbase);
            INSERT(s01, 2 * p + 0, rbase + 32);
            INSERT(s11, 2 * p + 1, rbase + 32);
        }
        __syncthreads();     // all warps done with buf[b] before re-staging
    }

    // ---- dump per-warp candidate lists ----
    __syncwarp();
    for (int e = tx; e < 4 * TOPK; e += 32) {
        g_cv[(blockIdx.x * NW + w) * 4 * TOPK + e] = wv[w * 4 * TOPK + e];
        g_ci[(blockIdx.x * NW + w) * 4 * TOPK + e] = wi[w * 4 * TOPK + e];
    }
    __threadfence();

    __shared__ unsigned s_last;
    if (tid == 0) {
        unsigned old = atomicInc(&g_ctr, NBLK - 1);
        s_last = (old == NBLK - 1) ? 1u : 0u;
    }
    __syncthreads();
    if (!s_last) return;
    __threadfence();

    // ---- final merge: 16 threads per query over 148 blocks x 2 lists ----
    int q = tid >> 4, part = tid & 15;
    int qgq = q >> 2, qq = q & 3;
    float lv[TOPK]; int li[TOPK];
    #pragma unroll
    for (int j = 0; j < TOPK; j++) { lv[j] = NEG_HUGE; li[j] = 0x7fffffff; }
    for (int blk = part; blk < NBLK; blk += 16) {
        #pragma unroll
        for (int rsel = 0; rsel < 2; rsel++) {
            int wl = qgq * 2 + rsel;
            int base = ((blk * NW + wl) * 4 + qq) * TOPK;
            #pragma unroll
            for (int s = 0; s < TOPK; s++) {
                float v = g_cv[base + s]; int gi = g_ci[base + s];
                float mn = lv[0]; int ms = 0;
                #pragma unroll
                for (int j = 1; j < TOPK; j++) if (lv[j] < mn) { mn = lv[j]; ms = j; }
                if (v > mn) { lv[ms] = v; li[ms] = gi; }
            }
        }
    }
    float* mv = buf;                          // tile buffers reusable now
    int*   mi = (int*)(buf + THREADS * TOPK);
    #pragma unroll
    for (int j = 0; j < TOPK; j++) { mv[tid * TOPK + j] = lv[j]; mi[tid * TOPK + j] = li[j]; }
    __syncthreads();

    if (part == 0) {
        float l3[TOPK]; int i3[TOPK];
        #pragma unroll
        for (int j = 0; j < TOPK; j++) { l3[j] = NEG_HUGE; i3[j] = 0x7fffffff; }
        for (int t = 0; t < 16 * TOPK; t++) {
            float v = mv[(q * 16) * TOPK + t]; int gi = mi[(q * 16) * TOPK + t];
            float mn = l3[0]; int ms = 0;
            #pragma unroll
            for (int j = 1; j < TOPK; j++) if (l3[j] < mn) { mn = l3[j]; ms = j; }
            if (v > mn) { l3[ms] = v; i3[ms] = gi; }
        }
        // sort desc, ties -> lower index (matches lax.top_k)
        for (int a = 0; a < TOPK; a++) {
            int best = a;
            for (int bb = a + 1; bb < TOPK; bb++)
                if (l3[bb] > l3[best] ||
                    (l3[bb] == l3[best] && i3[bb] < i3[best])) best = bb;
            float tv = l3[a]; l3[a] = l3[best]; l3[best] = tv;
            int   ti = i3[a]; i3[a] = i3[best]; i3[best] = ti;
        }
        if (out_size >= 2 * NQ * TOPK) {
            for (int j = 0; j < TOPK; j++) {
                out[q * TOPK + j] = l3[j];
                out[NQ * TOPK + q * TOPK + j] = (float)i3[j];
            }
        } else {
            for (int j = 0; j < TOPK; j++)
                if (q * TOPK + j < out_size) out[q * TOPK + j] = l3[j];
        }
    }
}

extern "C" void kernel_launch(void* const* d_in, const int* in_sizes, int n_in,
                              void* d_out, int out_size) {
    const float* queries = (const float*)d_in[0];
    const float* corpus  = (const float*)d_in[1];
    int n = in_sizes[1] / EMB;
    int nTiles = (n + TILE - 1) / TILE;

    size_t smemBytes = (size_t)(2 * TILE * WPAD + EMB * NQ) * sizeof(float)
                     + (size_t)(NW * 4 * TOPK) * (sizeof(float) + sizeof(int));
    cudaFuncSetAttribute(retr_kernel,
                         cudaFuncAttributeMaxDynamicSharedMemorySize, (int)smemBytes);

    retr_kernel<<<NBLK, THREADS, smemBytes>>>(queries, corpus, (float*)d_out,
                                              out_size, n, nTiles);
}